// round 3
// baseline (speedup 1.0000x reference)
#include <cuda_runtime.h>
#include <cuda_bf16.h>
#include <cstdint>

#define DIMC 512
#define HIDC 1024
#define NBATCH 16
#define NPIX 65536

// ---------------- scratch ----------------
__device__ __nv_bfloat16 g_h[(size_t)NPIX*DIMC];     // LN1 output (bf16)
__device__ uint8_t g_an[(size_t)NPIX*DIMC];          // row-normalized LN2 out (fp8, GEMM1 A)
__device__ uint8_t g_hidden[(size_t)NPIX*HIDC];      // gelu(sim*si) (fp8, GEMM2 A)
__device__ uint8_t g_winT[(size_t)HIDC*DIMC];        // [N=HID, K=DIM] col-normalized (fp8)
__device__ uint8_t g_woutT[(size_t)DIMC*HIDC];       // [N=DIM, K=HID] col-normalized (fp8)
__device__ float g_gp[NBATCH*DIMC];
__device__ float g_rowsq[NPIX];

// ---------------- helpers ----------------
__device__ __forceinline__ float wredsum(float v) {
#pragma unroll
    for (int o = 16; o > 0; o >>= 1) v += __shfl_xor_sync(0xffffffffu, v, o);
    return v;
}
__device__ __forceinline__ float4 ld_bf4(const __nv_bfloat16* p) {
    uint2 u = *(const uint2*)p;
    __nv_bfloat162 lo = *(__nv_bfloat162*)&u.x;
    __nv_bfloat162 hi = *(__nv_bfloat162*)&u.y;
    return make_float4(__bfloat162float(lo.x), __bfloat162float(lo.y),
                       __bfloat162float(hi.x), __bfloat162float(hi.y));
}
__device__ __forceinline__ void st_bf4(__nv_bfloat16* p, float a, float b, float c, float d) {
    __nv_bfloat162 lo = __floats2bfloat162_rn(a, b);
    __nv_bfloat162 hi = __floats2bfloat162_rn(c, d);
    uint2 u; u.x = *(uint32_t*)&lo; u.y = *(uint32_t*)&hi;
    *(uint2*)p = u;
}
__device__ __forceinline__ float gelu_exact(float u) {
    return 0.5f * u * (1.0f + erff(u * 0.70710678118654752f));
}
// pack 2 floats into e4m3x2 (lo = x, hi = y)
__device__ __forceinline__ uint16_t f2e4m3x2(float x, float y) {
    uint16_t r;
    asm("cvt.rn.satfinite.e4m3x2.f32 %0, %1, %2;" : "=h"(r) : "f"(y), "f"(x));
    return r;
}
__device__ __forceinline__ uint8_t f2e4m3(float x) {
    return (uint8_t)f2e4m3x2(x, 0.f);
}

// ---------------- K0: weight col-norm -> transposed fp8 ----------------------
// warp per column j of proto_in [DIMC, HIDC]; writes g_winT[j][*]
__global__ void k_norm_win(const float* __restrict__ p) {
    int w = threadIdx.x >> 5, lane = threadIdx.x & 31;
    int j = blockIdx.x * 8 + w;
    float v[16]; float ss = 0.f;
#pragma unroll
    for (int t = 0; t < 16; t++) { v[t] = p[(size_t)(lane + 32*t)*HIDC + j]; ss += v[t]*v[t]; }
    ss = wredsum(ss);
    float inv = 1.f / fmaxf(sqrtf(ss), 1e-12f);
#pragma unroll
    for (int t = 0; t < 16; t++)
        g_winT[(size_t)j*DIMC + lane + 32*t] = f2e4m3(v[t]*inv);
}
// warp per column c of proto_out [HIDC, DIMC]; also zero g_gp
__global__ void k_norm_wout(const float* __restrict__ p) {
    int gid = blockIdx.x * blockDim.x + threadIdx.x;
    if (gid < NBATCH*DIMC) g_gp[gid] = 0.f;
    int w = threadIdx.x >> 5, lane = threadIdx.x & 31;
    int c = blockIdx.x * 8 + w;
    float v[32]; float ss = 0.f;
#pragma unroll
    for (int t = 0; t < 32; t++) { v[t] = p[(size_t)(lane + 32*t)*DIMC + c]; ss += v[t]*v[t]; }
    ss = wredsum(ss);
    float inv = 1.f / fmaxf(sqrtf(ss), 1e-12f);
#pragma unroll
    for (int t = 0; t < 32; t++)
        g_woutT[(size_t)c*HIDC + lane + 32*t] = f2e4m3(v[t]*inv);
}

// ---------------- K1: LayerNorm1 -> g_h (bf16) + fused global-pool ----------
__global__ void k_ln1(const float* __restrict__ x, const float* __restrict__ w,
                      const float* __restrict__ bb) {
    int rowid = blockIdx.x;
    int b = rowid >> 6;
    int warp = threadIdx.x >> 5, lane = threadIdx.x & 31;
    __shared__ float sgp[DIMC];
    sgp[threadIdx.x] = 0.f; sgp[threadIdx.x + 256] = 0.f;
    __syncthreads();
    int cb = lane * 4;
    float4 wv[4], bv[4];
#pragma unroll
    for (int i = 0; i < 4; i++) {
        wv[i] = *(const float4*)(w + cb + i*128);
        bv[i] = *(const float4*)(bb + cb + i*128);
    }
    float gacc[16];
#pragma unroll
    for (int i = 0; i < 16; i++) gacc[i] = 0.f;
    for (int px = 0; px < 8; ++px) {
        size_t p = (size_t)rowid * 64 + warp * 8 + px;
        const float4* xp = (const float4*)(x + p * DIMC);
        float4 v[4];
        float s = 0.f, sq = 0.f;
#pragma unroll
        for (int i = 0; i < 4; i++) {
            v[i] = xp[lane + i*32];
            s  += v[i].x + v[i].y + v[i].z + v[i].w;
            sq += v[i].x*v[i].x + v[i].y*v[i].y + v[i].z*v[i].z + v[i].w*v[i].w;
        }
        s = wredsum(s); sq = wredsum(sq);
        float m = s * (1.f/512.f);
        float var = sq * (1.f/512.f) - m*m;
        float rstd = rsqrtf(var + 1e-5f);
        __nv_bfloat16* hp = g_h + p * DIMC;
#pragma unroll
        for (int i = 0; i < 4; i++) {
            float h0 = (v[i].x - m)*rstd*wv[i].x + bv[i].x;
            float h1 = (v[i].y - m)*rstd*wv[i].y + bv[i].y;
            float h2 = (v[i].z - m)*rstd*wv[i].z + bv[i].z;
            float h3 = (v[i].w - m)*rstd*wv[i].w + bv[i].w;
            st_bf4(hp + cb + i*128, h0, h1, h2, h3);
            gacc[i*4+0] += h0; gacc[i*4+1] += h1; gacc[i*4+2] += h2; gacc[i*4+3] += h3;
        }
    }
#pragma unroll
    for (int i = 0; i < 4; i++)
#pragma unroll
        for (int q = 0; q < 4; q++)
            atomicAdd(&sgp[cb + i*128 + q], gacc[i*4+q]);
    __syncthreads();
    atomicAdd(&g_gp[b*DIMC + threadIdx.x], sgp[threadIdx.x]);
    atomicAdd(&g_gp[b*DIMC + threadIdx.x + 256], sgp[threadIdx.x + 256]);
}

// ---------------- K2: spatial + residual1 + LN2 + row L2 norm ---------------
// writes x2 (fp32) to d_out, writes g_an (fp8), zeroes g_rowsq
__global__ void k_spatial(const float* __restrict__ x, const float* __restrict__ alpha,
                          const float* __restrict__ w2, const float* __restrict__ b2,
                          const float* __restrict__ gamma, float* __restrict__ out) {
    int rowid = blockIdx.x;
    int b = rowid >> 6, y = rowid & 63;
    int warp = threadIdx.x >> 5, lane = threadIdx.x & 31;
    int cb = lane * 4;
    float4 av[4], wv[4], bv[4], gv[4], gpv[4];
#pragma unroll
    for (int i = 0; i < 4; i++) {
        av[i] = *(const float4*)(alpha + cb + i*128);
        wv[i] = *(const float4*)(w2 + cb + i*128);
        bv[i] = *(const float4*)(b2 + cb + i*128);
        gv[i] = *(const float4*)(gamma + cb + i*128);
        const float4 gp4 = *(const float4*)(g_gp + b*DIMC + cb + i*128);
        gpv[i] = make_float4(gp4.x*(1.f/4096.f), gp4.y*(1.f/4096.f),
                             gp4.z*(1.f/4096.f), gp4.w*(1.f/4096.f));
    }
    for (int px = 0; px < 8; ++px) {
        int xc = warp * 8 + px;
        size_t p = (size_t)rowid * 64 + xc;
        const __nv_bfloat16* hC = g_h + p * DIMC;
        bool hasU = (y > 0), hasD = (y < 63), hasL = (xc > 0), hasR = (xc < 63);
        const float4* xp = (const float4*)(x + p * DIMC);
        float4 v[4];
        float s = 0.f, sq = 0.f;
#pragma unroll
        for (int i = 0; i < 4; i++) {
            int off = cb + i*128;
            float4 c4 = ld_bf4(hC + off);
            float4 u4 = hasU ? ld_bf4(hC - 64*DIMC + off) : make_float4(0,0,0,0);
            float4 d4 = hasD ? ld_bf4(hC + 64*DIMC + off) : make_float4(0,0,0,0);
            float4 l4 = hasL ? ld_bf4(hC - DIMC + off)    : make_float4(0,0,0,0);
            float4 r4 = hasR ? ld_bf4(hC + DIMC + off)    : make_float4(0,0,0,0);
            float4 fe;
            fe.x = fabsf(c4.x-u4.x)+fabsf(c4.x-d4.x)+fabsf(c4.x-l4.x)+fabsf(c4.x-r4.x);
            fe.y = fabsf(c4.y-u4.y)+fabsf(c4.y-d4.y)+fabsf(c4.y-l4.y)+fabsf(c4.y-r4.y);
            fe.z = fabsf(c4.z-u4.z)+fabsf(c4.z-d4.z)+fabsf(c4.z-l4.z)+fabsf(c4.z-r4.z);
            fe.w = fabsf(c4.w-u4.w)+fabsf(c4.w-d4.w)+fabsf(c4.w-l4.w)+fabsf(c4.w-r4.w);
            float4 sp;
            sp.x = fe.x*av[i].x + gpv[i].x*(1.f-av[i].x);
            sp.y = fe.y*av[i].y + gpv[i].y*(1.f-av[i].y);
            sp.z = fe.z*av[i].z + gpv[i].z*(1.f-av[i].z);
            sp.w = fe.w*av[i].w + gpv[i].w*(1.f-av[i].w);
            float4 xv = xp[lane + i*32];
            v[i].x = xv.x + gv[i].x*sp.x;
            v[i].y = xv.y + gv[i].y*sp.y;
            v[i].z = xv.z + gv[i].z*sp.z;
            v[i].w = xv.w + gv[i].w*sp.w;
            s  += v[i].x + v[i].y + v[i].z + v[i].w;
            sq += v[i].x*v[i].x + v[i].y*v[i].y + v[i].z*v[i].z + v[i].w*v[i].w;
        }
        s = wredsum(s); sq = wredsum(sq);
        float m = s * (1.f/512.f);
        float var = sq * (1.f/512.f) - m*m;
        float rstd = rsqrtf(var + 1e-5f);
        float h2v[16];
        float ss = 0.f;
#pragma unroll
        for (int i = 0; i < 4; i++) {
            h2v[i*4+0] = (v[i].x - m)*rstd*wv[i].x + bv[i].x;
            h2v[i*4+1] = (v[i].y - m)*rstd*wv[i].y + bv[i].y;
            h2v[i*4+2] = (v[i].z - m)*rstd*wv[i].z + bv[i].z;
            h2v[i*4+3] = (v[i].w - m)*rstd*wv[i].w + bv[i].w;
            ss += h2v[i*4+0]*h2v[i*4+0] + h2v[i*4+1]*h2v[i*4+1]
                + h2v[i*4+2]*h2v[i*4+2] + h2v[i*4+3]*h2v[i*4+3];
        }
        ss = wredsum(ss);
        float inv = 1.f / fmaxf(sqrtf(ss), 1e-12f);
        float4* op = (float4*)(out + p * DIMC);
        uint32_t* ap = (uint32_t*)(g_an + p * DIMC);
#pragma unroll
        for (int i = 0; i < 4; i++) {
            op[lane + i*32] = v[i];
            uint16_t lo = f2e4m3x2(h2v[i*4+0]*inv, h2v[i*4+1]*inv);
            uint16_t hi = f2e4m3x2(h2v[i*4+2]*inv, h2v[i*4+3]*inv);
            ap[lane + i*32] = (uint32_t)lo | ((uint32_t)hi << 16);
        }
        if (lane == 0) g_rowsq[p] = 0.f;
    }
}

// ================= FP8 GEMM: mma.sync m16n8k32 e4m3, 128x128x128 tiles ======
#define NSTAGE 3
#define STGB 32768   // 16KB A + 16KB B per stage

__device__ __forceinline__ void cpa16(uint32_t s, const void* g) {
    asm volatile("cp.async.cg.shared.global [%0], [%1], 16;\n" :: "r"(s), "l"(g));
}
__device__ __forceinline__ uint32_t swz128(uint32_t o) { return o ^ ((o >> 3) & 0x70); }

#define QMMA(d, a, b0v, b1v)                                               \
    asm volatile(                                                          \
        "mma.sync.aligned.m16n8k32.row.col.f32.e4m3.e4m3.f32 "             \
        "{%0,%1,%2,%3},{%4,%5,%6,%7},{%8,%9},{%0,%1,%2,%3};\n"             \
        : "+f"(d[0]), "+f"(d[1]), "+f"(d[2]), "+f"(d[3])                   \
        : "r"(a[0]), "r"(a[1]), "r"(a[2]), "r"(a[3]), "r"(b0v), "r"(b1v))

#define LDSM4(r0, r1, r2, r3, addr)                                        \
    asm volatile("ldmatrix.sync.aligned.m8n8.x4.shared.b16 {%0,%1,%2,%3},[%4];\n" \
                 : "=r"(r0), "=r"(r1), "=r"(r2), "=r"(r3) : "r"(addr))

// EPI=1: A=g_an [M,512], B=g_winT [1024,512] -> gelu(acc*sc) -> g_hidden fp8 + rowsq
// EPI=2: A=g_hidden [M,1024], B=g_woutT [512,1024] -> out += gamma*acc*sc*rsqrt(rowsq)
template <int KDIM, int EPI>
__global__ __launch_bounds__(256) void k_gemm_fp8(const float* __restrict__ sc_p,
                                                  const float* __restrict__ gamma,
                                                  float* __restrict__ outp) {
    extern __shared__ __align__(1024) uint8_t sm[];
    const uint8_t* __restrict__ A = (EPI == 1) ? g_an : g_hidden;
    const uint8_t* __restrict__ B = (EPI == 1) ? g_winT : g_woutT;
    const int NDIM = (EPI == 1) ? HIDC : DIMC;

    int tid = threadIdx.x, wid = tid >> 5, lane = tid & 31;
    int bm = blockIdx.y * 128, bn = blockIdx.x * 128;
    int wr = wid & 3, wc = wid >> 2;   // warp tile 32(m) x 64(n)
    uint32_t smem_u = (uint32_t)__cvta_generic_to_shared(sm);

    // cp.async maps: thread -> row tid>>1, chunks (tid&1)*4 + 0..3 (16B each)
    int lrow = tid >> 1;
    int lc4  = (tid & 1) * 4;
    const uint8_t* gA = A + (size_t)(bm + lrow) * KDIM + lc4 * 16;
    const uint8_t* gB = B + (size_t)(bn + lrow) * KDIM + lc4 * 16;
    uint32_t soA[4], soB[4];
#pragma unroll
    for (int c = 0; c < 4; c++) {
        uint32_t o = (uint32_t)lrow * 128 + (lc4 + c) * 16;
        soA[c] = swz128(o);
        soB[c] = 16384 + swz128(o);
    }

    float acc[2][8][4];
#pragma unroll
    for (int mi = 0; mi < 2; mi++)
#pragma unroll
        for (int ni = 0; ni < 8; ni++)
#pragma unroll
            for (int q = 0; q < 4; q++) acc[mi][ni][q] = 0.f;

    const int nkt = KDIM / 128;

    // prefetch stages 0,1
#pragma unroll
    for (int pf = 0; pf < 2; pf++) {
        uint32_t base = smem_u + pf * STGB;
        int ko = pf * 128;
#pragma unroll
        for (int c = 0; c < 4; c++) {
            cpa16(base + soA[c], gA + ko + c * 16);
            cpa16(base + soB[c], gB + ko + c * 16);
        }
        asm volatile("cp.async.commit_group;\n");
    }

    // ldmatrix base offsets
    int arow = wr * 32 + (lane & 15);
    int brow = wc * 64 + (lane & 15);
    int colh = (lane >> 4) * 16;

    for (int kt = 0; kt < nkt; kt++) {
        if (kt == nkt - 1) asm volatile("cp.async.wait_group 0;\n");
        else               asm volatile("cp.async.wait_group 1;\n");
        __syncthreads();
        if (kt + 2 < nkt) {
            uint32_t base = smem_u + ((kt + 2) % NSTAGE) * STGB;
            int ko = (kt + 2) * 128;
#pragma unroll
            for (int c = 0; c < 4; c++) {
                cpa16(base + soA[c], gA + ko + c * 16);
                cpa16(base + soB[c], gB + ko + c * 16);
            }
            asm volatile("cp.async.commit_group;\n");
        }
        uint32_t base = smem_u + (kt % NSTAGE) * STGB;
#pragma unroll
        for (int ks = 0; ks < 4; ks++) {
            int col = ks * 32 + colh;
            uint32_t a[2][4];
#pragma unroll
            for (int mi = 0; mi < 2; mi++) {
                uint32_t o = (uint32_t)(arow + mi * 16) * 128 + col;
                LDSM4(a[mi][0], a[mi][1], a[mi][2], a[mi][3], base + swz128(o));
            }
#pragma unroll
            for (int nj = 0; nj < 4; nj++) {
                uint32_t r0, r1, r2, r3;
                uint32_t o = (uint32_t)(brow + nj * 16) * 128 + col;
                LDSM4(r0, r1, r2, r3, base + 16384 + swz128(o));
#pragma unroll
                for (int mi = 0; mi < 2; mi++) {
                    QMMA(acc[mi][2*nj],     a[mi], r0, r2);
                    QMMA(acc[mi][2*nj + 1], a[mi], r1, r3);
                }
            }
        }
        __syncthreads();
    }

    float sc = __ldg(sc_p);
    if (EPI == 1) {
#pragma unroll
        for (int mi = 0; mi < 2; mi++) {
            int r0 = bm + wr * 32 + mi * 16 + (lane >> 2);
            int r1 = r0 + 8;
            float s0 = 0.f, s1 = 0.f;
#pragma unroll
            for (int ni = 0; ni < 8; ni++) {
                int c = bn + wc * 64 + ni * 8 + (lane & 3) * 2;
                float g0 = gelu_exact(acc[mi][ni][0] * sc);
                float g1 = gelu_exact(acc[mi][ni][1] * sc);
                float g2 = gelu_exact(acc[mi][ni][2] * sc);
                float g3 = gelu_exact(acc[mi][ni][3] * sc);
                *(uint16_t*)(g_hidden + (size_t)r0 * HIDC + c) = f2e4m3x2(g0, g1);
                *(uint16_t*)(g_hidden + (size_t)r1 * HIDC + c) = f2e4m3x2(g2, g3);
                s0 += g0*g0 + g1*g1;
                s1 += g2*g2 + g3*g3;
            }
            s0 += __shfl_xor_sync(0xffffffffu, s0, 1);
            s0 += __shfl_xor_sync(0xffffffffu, s0, 2);
            s1 += __shfl_xor_sync(0xffffffffu, s1, 1);
            s1 += __shfl_xor_sync(0xffffffffu, s1, 2);
            if ((lane & 3) == 0) {
                atomicAdd(&g_rowsq[r0], s0);
                atomicAdd(&g_rowsq[r1], s1);
            }
        }
    } else {
#pragma unroll
        for (int mi = 0; mi < 2; mi++) {
            int r0 = bm + wr * 32 + mi * 16 + (lane >> 2);
            int r1 = r0 + 8;
            float inv0 = sc / fmaxf(sqrtf(g_rowsq[r0]), 1e-12f);
            float inv1 = sc / fmaxf(sqrtf(g_rowsq[r1]), 1e-12f);
#pragma unroll
            for (int ni = 0; ni < 8; ni++) {
                int c = bn + wc * 64 + ni * 8 + (lane & 3) * 2;
                float ga0 = gamma[c], ga1 = gamma[c + 1];
                size_t i00 = (size_t)r0 * DIMC + c;
                size_t i10 = (size_t)r1 * DIMC + c;
                outp[i00]     += ga0 * acc[mi][ni][0] * inv0;
                outp[i00 + 1] += ga1 * acc[mi][ni][1] * inv0;
                outp[i10]     += ga0 * acc[mi][ni][2] * inv1;
                outp[i10 + 1] += ga1 * acc[mi][ni][3] * inv1;
            }
        }
    }
    (void)NDIM;
}

// ---------------- launch ----------------
extern "C" void kernel_launch(void* const* d_in, const int* in_sizes, int n_in,
                              void* d_out, int out_size) {
    const float* x     = (const float*)d_in[0];
    const float* n1w   = (const float*)d_in[1];
    const float* n1b   = (const float*)d_in[2];
    const float* alpha = (const float*)d_in[3];
    const float* n2w   = (const float*)d_in[4];
    const float* n2b   = (const float*)d_in[5];
    const float* pin   = (const float*)d_in[6];
    const float* pout  = (const float*)d_in[7];
    const float* s_in  = (const float*)d_in[8];
    const float* s_out = (const float*)d_in[9];
    const float* gamma = (const float*)d_in[10];
    float* out = (float*)d_out;

    cudaFuncSetAttribute(k_gemm_fp8<512, 1>,  cudaFuncAttributeMaxDynamicSharedMemorySize, NSTAGE*STGB);
    cudaFuncSetAttribute(k_gemm_fp8<1024, 2>, cudaFuncAttributeMaxDynamicSharedMemorySize, NSTAGE*STGB);

    k_norm_win<<<HIDC / 8, 256>>>(pin);
    k_norm_wout<<<DIMC / 8, 256>>>(pout);
    k_ln1<<<NBATCH * 64, 256>>>(x, n1w, n1b);
    k_spatial<<<NBATCH * 64, 256>>>(x, alpha, n2w, n2b, gamma, out);
    k_gemm_fp8<512, 1><<<dim3(HIDC / 128, NPIX / 128), 256, NSTAGE*STGB>>>(s_in, nullptr, nullptr);
    k_gemm_fp8<1024, 2><<<dim3(DIMC / 128, NPIX / 128), 256, NSTAGE*STGB>>>(s_out, gamma, out);
}

// round 4
// speedup vs baseline: 1.0443x; 1.0443x over previous
#include <cuda_runtime.h>
#include <cuda_bf16.h>
#include <cstdint>

#define DIMC 512
#define HIDC 1024
#define NBATCH 16
#define NPIX 65536

// ---------------- scratch ----------------
__device__ __nv_bfloat16 g_h[(size_t)NPIX*DIMC];     // LN1 output (bf16)
__device__ uint8_t g_an[(size_t)NPIX*DIMC];          // row-normalized LN2 out (fp8)
__device__ uint8_t g_hidden[(size_t)NPIX*HIDC];      // gelu(sim*si) (fp8)
__device__ uint8_t g_winT[(size_t)HIDC*DIMC];        // [N=HID, K=DIM] col-normalized fp8
__device__ uint8_t g_woutT[(size_t)DIMC*HIDC];       // [N=DIM, K=HID] col-normalized fp8
__device__ float g_gp[NBATCH*DIMC];
__device__ float g_rowsq[NPIX];
__device__ float g_csin[HIDC];                       // col sumsq of proto_in
__device__ float g_csout[DIMC];                      // col sumsq of proto_out

// ---------------- helpers ----------------
__device__ __forceinline__ float wredsum(float v) {
#pragma unroll
    for (int o = 16; o > 0; o >>= 1) v += __shfl_xor_sync(0xffffffffu, v, o);
    return v;
}
__device__ __forceinline__ float4 ld_bf4(const __nv_bfloat16* p) {
    uint2 u = *(const uint2*)p;
    __nv_bfloat162 lo = *(__nv_bfloat162*)&u.x;
    __nv_bfloat162 hi = *(__nv_bfloat162*)&u.y;
    return make_float4(__bfloat162float(lo.x), __bfloat162float(lo.y),
                       __bfloat162float(hi.x), __bfloat162float(hi.y));
}
__device__ __forceinline__ void st_bf4(__nv_bfloat16* p, float a, float b, float c, float d) {
    __nv_bfloat162 lo = __floats2bfloat162_rn(a, b);
    __nv_bfloat162 hi = __floats2bfloat162_rn(c, d);
    uint2 u; u.x = *(uint32_t*)&lo; u.y = *(uint32_t*)&hi;
    *(uint2*)p = u;
}
__device__ __forceinline__ float gelu_exact(float u) {
    return 0.5f * u * (1.0f + erff(u * 0.70710678118654752f));
}
__device__ __forceinline__ uint16_t f2e4m3x2(float x, float y) {  // lo byte = x
    uint16_t r;
    asm("cvt.rn.satfinite.e4m3x2.f32 %0, %1, %2;" : "=h"(r) : "f"(y), "f"(x));
    return r;
}

// ---------------- KZ: zero accumulators --------------------------------------
__global__ void kz() {
    int t = threadIdx.x;
    for (int i = t; i < HIDC; i += 256) g_csin[i] = 0.f;
    for (int i = t; i < DIMC; i += 256) g_csout[i] = 0.f;
    for (int i = t; i < NBATCH*DIMC; i += 256) g_gp[i] = 0.f;
}

// ---------------- K-colsq: column sum-of-squares (coalesced) ------------------
__global__ void k_colsq(const float* __restrict__ pin, const float* __restrict__ pout) {
    __shared__ float s[HIDC];
    int b = blockIdx.x, t = threadIdx.x;
    if (b < 32) {               // proto_in rows b*16..+15  [512, 1024]
        for (int i = t; i < HIDC; i += 256) s[i] = 0.f;
        __syncthreads();
        const float* src = pin + (size_t)b * 16 * HIDC;
        for (int i = t; i < 16 * HIDC; i += 256) {
            float v = src[i];
            atomicAdd(&s[i & (HIDC - 1)], v * v);
        }
        __syncthreads();
        for (int i = t; i < HIDC; i += 256) atomicAdd(&g_csin[i], s[i]);
    } else {                    // proto_out rows (b-32)*16..+15  [1024, 512]
        for (int i = t; i < DIMC; i += 256) s[i] = 0.f;
        __syncthreads();
        const float* src = pout + (size_t)(b - 32) * 16 * DIMC;
        for (int i = t; i < 16 * DIMC; i += 256) {
            float v = src[i];
            atomicAdd(&s[i & (DIMC - 1)], v * v);
        }
        __syncthreads();
        for (int i = t; i < DIMC; i += 256) atomicAdd(&g_csout[i], s[i]);
    }
}

// ---------------- K-wtrans: normalized transpose to fp8 (smem tile) -----------
// tile = 32 (k) x 64 (j). pin: 256 blocks; pout: 256 blocks.
__global__ void k_wtrans(const float* __restrict__ pin, const float* __restrict__ pout) {
    __shared__ float tile[32][65];
    int b = blockIdx.x, t = threadIdx.x;
    if (b < 256) {
        int jt = (b & 15) * 64, kt = (b >> 4) * 32;
        int jc = t & 63;
        for (int rr = t >> 6; rr < 32; rr += 4)
            tile[rr][jc] = pin[(size_t)(kt + rr) * HIDC + jt + jc];
        __syncthreads();
        int j = t >> 2, kq = (t & 3) * 8;
        float inv = 1.f / fmaxf(sqrtf(g_csin[jt + j]), 1e-12f);
        float v[8];
#pragma unroll
        for (int q = 0; q < 8; q++) v[q] = tile[kq + q][j] * inv;
        uint32_t u0 = (uint32_t)f2e4m3x2(v[0], v[1]) | ((uint32_t)f2e4m3x2(v[2], v[3]) << 16);
        uint32_t u1 = (uint32_t)f2e4m3x2(v[4], v[5]) | ((uint32_t)f2e4m3x2(v[6], v[7]) << 16);
        *(uint2*)(g_winT + (size_t)(jt + j) * DIMC + kt + kq) = make_uint2(u0, u1);
    } else {
        int b2 = b - 256;
        int jt = (b2 & 7) * 64, kt = (b2 >> 3) * 32;
        int jc = t & 63;
        for (int rr = t >> 6; rr < 32; rr += 4)
            tile[rr][jc] = pout[(size_t)(kt + rr) * DIMC + jt + jc];
        __syncthreads();
        int j = t >> 2, kq = (t & 3) * 8;
        float inv = 1.f / fmaxf(sqrtf(g_csout[jt + j]), 1e-12f);
        float v[8];
#pragma unroll
        for (int q = 0; q < 8; q++) v[q] = tile[kq + q][j] * inv;
        uint32_t u0 = (uint32_t)f2e4m3x2(v[0], v[1]) | ((uint32_t)f2e4m3x2(v[2], v[3]) << 16);
        uint32_t u1 = (uint32_t)f2e4m3x2(v[4], v[5]) | ((uint32_t)f2e4m3x2(v[6], v[7]) << 16);
        *(uint2*)(g_woutT + (size_t)(jt + j) * HIDC + kt + kq) = make_uint2(u0, u1);
    }
}

// ---------------- K1: LayerNorm1 -> g_h (bf16) + fused global-pool ----------
__global__ __launch_bounds__(256, 2) void k_ln1(const float* __restrict__ x,
                                                const float* __restrict__ w,
                                                const float* __restrict__ bb) {
    __shared__ float s_w[DIMC], s_b[DIMC], sgp[DIMC];
    int rowid = blockIdx.x;
    int b = rowid >> 6;
    int t = threadIdx.x;
    for (int i = t; i < DIMC; i += 256) { s_w[i] = w[i]; s_b[i] = bb[i]; sgp[i] = 0.f; }
    __syncthreads();
    int warp = t >> 5, lane = t & 31, cb = lane * 4;
    float gacc[16];
#pragma unroll
    for (int i = 0; i < 16; i++) gacc[i] = 0.f;
    for (int px = 0; px < 8; ++px) {
        size_t p = (size_t)rowid * 64 + warp * 8 + px;
        const float4* xp = (const float4*)(x + p * DIMC);
        float4 v[4];
        float s = 0.f, sq = 0.f;
#pragma unroll
        for (int i = 0; i < 4; i++) {
            v[i] = xp[lane + i*32];
            s  += v[i].x + v[i].y + v[i].z + v[i].w;
            sq += v[i].x*v[i].x + v[i].y*v[i].y + v[i].z*v[i].z + v[i].w*v[i].w;
        }
        s = wredsum(s); sq = wredsum(sq);
        float m = s * (1.f/512.f);
        float rstd = rsqrtf(sq * (1.f/512.f) - m*m + 1e-5f);
        __nv_bfloat16* hp = g_h + p * DIMC;
#pragma unroll
        for (int i = 0; i < 4; i++) {
            float4 w4 = *(const float4*)&s_w[cb + i*128];
            float4 b4 = *(const float4*)&s_b[cb + i*128];
            float h0 = (v[i].x - m)*rstd*w4.x + b4.x;
            float h1 = (v[i].y - m)*rstd*w4.y + b4.y;
            float h2 = (v[i].z - m)*rstd*w4.z + b4.z;
            float h3 = (v[i].w - m)*rstd*w4.w + b4.w;
            st_bf4(hp + cb + i*128, h0, h1, h2, h3);
            gacc[i*4+0] += h0; gacc[i*4+1] += h1; gacc[i*4+2] += h2; gacc[i*4+3] += h3;
        }
    }
#pragma unroll
    for (int i = 0; i < 4; i++)
#pragma unroll
        for (int q = 0; q < 4; q++)
            atomicAdd(&sgp[cb + i*128 + q], gacc[i*4+q]);
    __syncthreads();
    atomicAdd(&g_gp[b*DIMC + t], sgp[t]);
    atomicAdd(&g_gp[b*DIMC + t + 256], sgp[t + 256]);
}

// ---------------- K2: spatial + residual1 + LN2 + row L2 norm ---------------
__global__ __launch_bounds__(256, 2) void k_spatial(const float* __restrict__ x,
                                                    const float* __restrict__ alpha,
                                                    const float* __restrict__ w2,
                                                    const float* __restrict__ b2,
                                                    const float* __restrict__ gamma,
                                                    float* __restrict__ out) {
    __shared__ float s_al[DIMC], s_gpc[DIMC], s_w[DIMC], s_b[DIMC], s_g[DIMC];
    int rowid = blockIdx.x;
    int b = rowid >> 6, y = rowid & 63;
    int t = threadIdx.x;
    for (int i = t; i < DIMC; i += 256) {
        float al = alpha[i];
        s_al[i] = al;
        s_gpc[i] = g_gp[b*DIMC + i] * (1.f - al) * (1.f/4096.f);
        s_w[i] = w2[i]; s_b[i] = b2[i]; s_g[i] = gamma[i];
    }
    __syncthreads();
    int warp = t >> 5, lane = t & 31, cb = lane * 4;
    for (int px = 0; px < 8; ++px) {
        int xc = warp * 8 + px;
        size_t p = (size_t)rowid * 64 + xc;
        const __nv_bfloat16* hC = g_h + p * DIMC;
        bool hasU = (y > 0), hasD = (y < 63), hasL = (xc > 0), hasR = (xc < 63);
        const float4* xp = (const float4*)(x + p * DIMC);
        float4 v[4];
        float s = 0.f, sq = 0.f;
#pragma unroll
        for (int i = 0; i < 4; i++) {
            int off = cb + i*128;
            float4 c4 = ld_bf4(hC + off);
            float4 u4 = hasU ? ld_bf4(hC - 64*DIMC + off) : make_float4(0,0,0,0);
            float4 d4 = hasD ? ld_bf4(hC + 64*DIMC + off) : make_float4(0,0,0,0);
            float4 l4 = hasL ? ld_bf4(hC - DIMC + off)    : make_float4(0,0,0,0);
            float4 r4 = hasR ? ld_bf4(hC + DIMC + off)    : make_float4(0,0,0,0);
            float4 al4 = *(const float4*)&s_al[off];
            float4 gp4 = *(const float4*)&s_gpc[off];
            float4 g4  = *(const float4*)&s_g[off];
            float4 xv = xp[lane + i*32];
            float fe, sp;
            fe = fabsf(c4.x-u4.x)+fabsf(c4.x-d4.x)+fabsf(c4.x-l4.x)+fabsf(c4.x-r4.x);
            sp = fe*al4.x + gp4.x;  v[i].x = xv.x + g4.x*sp;
            fe = fabsf(c4.y-u4.y)+fabsf(c4.y-d4.y)+fabsf(c4.y-l4.y)+fabsf(c4.y-r4.y);
            sp = fe*al4.y + gp4.y;  v[i].y = xv.y + g4.y*sp;
            fe = fabsf(c4.z-u4.z)+fabsf(c4.z-d4.z)+fabsf(c4.z-l4.z)+fabsf(c4.z-r4.z);
            sp = fe*al4.z + gp4.z;  v[i].z = xv.z + g4.z*sp;
            fe = fabsf(c4.w-u4.w)+fabsf(c4.w-d4.w)+fabsf(c4.w-l4.w)+fabsf(c4.w-r4.w);
            sp = fe*al4.w + gp4.w;  v[i].w = xv.w + g4.w*sp;
            s  += v[i].x + v[i].y + v[i].z + v[i].w;
            sq += v[i].x*v[i].x + v[i].y*v[i].y + v[i].z*v[i].z + v[i].w*v[i].w;
        }
        s = wredsum(s); sq = wredsum(sq);
        float m = s * (1.f/512.f);
        float rstd = rsqrtf(sq * (1.f/512.f) - m*m + 1e-5f);
        // pass2: out store + LN2 sumsq
        float4* op = (float4*)(out + p * DIMC);
        float ss = 0.f;
#pragma unroll
        for (int i = 0; i < 4; i++) {
            int off = cb + i*128;
            op[lane + i*32] = v[i];
            float4 w4 = *(const float4*)&s_w[off];
            float4 b4 = *(const float4*)&s_b[off];
            float h0 = (v[i].x - m)*rstd*w4.x + b4.x;
            float h1 = (v[i].y - m)*rstd*w4.y + b4.y;
            float h2 = (v[i].z - m)*rstd*w4.z + b4.z;
            float h3 = (v[i].w - m)*rstd*w4.w + b4.w;
            ss += h0*h0 + h1*h1 + h2*h2 + h3*h3;
        }
        ss = wredsum(ss);
        float inv = 1.f / fmaxf(sqrtf(ss), 1e-12f);
        uint32_t* ap = (uint32_t*)(g_an + p * DIMC);
#pragma unroll
        for (int i = 0; i < 4; i++) {
            int off = cb + i*128;
            float4 w4 = *(const float4*)&s_w[off];
            float4 b4 = *(const float4*)&s_b[off];
            float h0 = ((v[i].x - m)*rstd*w4.x + b4.x) * inv;
            float h1 = ((v[i].y - m)*rstd*w4.y + b4.y) * inv;
            float h2 = ((v[i].z - m)*rstd*w4.z + b4.z) * inv;
            float h3 = ((v[i].w - m)*rstd*w4.w + b4.w) * inv;
            ap[lane + i*32] = (uint32_t)f2e4m3x2(h0, h1) | ((uint32_t)f2e4m3x2(h2, h3) << 16);
        }
        if (lane == 0) g_rowsq[p] = 0.f;
    }
}

// ================= FP8 GEMM: CTA 128x256x128, warp tile 64x64 ================
#define NSTAGE 3
#define STGB 49152   // 16KB A + 32KB B per stage

__device__ __forceinline__ void cpa16(uint32_t s, const void* g) {
    asm volatile("cp.async.cg.shared.global [%0], [%1], 16;\n" :: "r"(s), "l"(g));
}
__device__ __forceinline__ uint32_t swz128(uint32_t o) { return o ^ ((o >> 3) & 0x70); }

#define QMMA(d, a, b0v, b1v)                                               \
    asm volatile(                                                          \
        "mma.sync.aligned.m16n8k32.row.col.f32.e4m3.e4m3.f32 "             \
        "{%0,%1,%2,%3},{%4,%5,%6,%7},{%8,%9},{%0,%1,%2,%3};\n"             \
        : "+f"(d[0]), "+f"(d[1]), "+f"(d[2]), "+f"(d[3])                   \
        : "r"(a[0]), "r"(a[1]), "r"(a[2]), "r"(a[3]), "r"(b0v), "r"(b1v))

#define LDSM4(r0, r1, r2, r3, addr)                                        \
    asm volatile("ldmatrix.sync.aligned.m8n8.x4.shared.b16 {%0,%1,%2,%3},[%4];\n" \
                 : "=r"(r0), "=r"(r1), "=r"(r2), "=r"(r3) : "r"(addr))

template <int KDIM, int EPI>
__global__ __launch_bounds__(256) void k_gemm_fp8(const float* __restrict__ sc_p,
                                                  const float* __restrict__ gamma,
                                                  float* __restrict__ outp) {
    extern __shared__ __align__(1024) uint8_t sm[];
    __shared__ float s_gam[256];
    const uint8_t* __restrict__ A  = (EPI == 1) ? g_an : g_hidden;
    const uint8_t* __restrict__ Bw = (EPI == 1) ? g_winT : g_woutT;

    int tid = threadIdx.x, wid = tid >> 5, lane = tid & 31;
    int bm = blockIdx.y * 128, bn = blockIdx.x * 256;
    int wr = wid & 1, wc = wid >> 1;   // warp tile 64(m) x 64(n)
    uint32_t smem_u = (uint32_t)__cvta_generic_to_shared(sm);
    if (EPI == 2) s_gam[tid] = gamma[bn + tid];

    int lrow = tid >> 1, lc4 = (tid & 1) * 4;
    const uint8_t* gA = A  + (size_t)(bm + lrow) * KDIM + lc4 * 16;
    const uint8_t* gB = Bw + (size_t)(bn + lrow) * KDIM + lc4 * 16;
    uint32_t soA[4], soB[4];
#pragma unroll
    for (int c = 0; c < 4; c++) {
        uint32_t o = (uint32_t)lrow * 128 + (lc4 + c) * 16;
        soA[c] = swz128(o);
        soB[c] = 16384 + swz128(o);
    }

    float acc[4][8][4];
#pragma unroll
    for (int mi = 0; mi < 4; mi++)
#pragma unroll
        for (int ni = 0; ni < 8; ni++)
#pragma unroll
            for (int q = 0; q < 4; q++) acc[mi][ni][q] = 0.f;

    const int nkt = KDIM / 128;
#pragma unroll
    for (int pf = 0; pf < 2; pf++) {
        uint32_t base = smem_u + pf * STGB;
        int ko = pf * 128;
#pragma unroll
        for (int c = 0; c < 4; c++) {
            cpa16(base + soA[c], gA + ko + c * 16);
            cpa16(base + soB[c], gB + ko + c * 16);
            cpa16(base + soB[c] + 16384, gB + (size_t)128 * KDIM + ko + c * 16);
        }
        asm volatile("cp.async.commit_group;\n");
    }

    for (int kt = 0; kt < nkt; kt++) {
        if (kt == nkt - 1) asm volatile("cp.async.wait_group 0;\n");
        else               asm volatile("cp.async.wait_group 1;\n");
        __syncthreads();
        if (kt + 2 < nkt) {
            uint32_t base = smem_u + ((kt + 2) % NSTAGE) * STGB;
            int ko = (kt + 2) * 128;
#pragma unroll
            for (int c = 0; c < 4; c++) {
                cpa16(base + soA[c], gA + ko + c * 16);
                cpa16(base + soB[c], gB + ko + c * 16);
                cpa16(base + soB[c] + 16384, gB + (size_t)128 * KDIM + ko + c * 16);
            }
            asm volatile("cp.async.commit_group;\n");
        }
        uint32_t base = smem_u + (kt % NSTAGE) * STGB;
#pragma unroll
        for (int ks = 0; ks < 4; ks++) {
            int col = ks * 32 + (lane >> 4) * 16;
            uint32_t a[4][4];
#pragma unroll
            for (int mi = 0; mi < 4; mi++) {
                uint32_t o = (uint32_t)(wr * 64 + mi * 16 + (lane & 15)) * 128 + col;
                LDSM4(a[mi][0], a[mi][1], a[mi][2], a[mi][3], base + swz128(o));
            }
#pragma unroll
            for (int nj = 0; nj < 4; nj++) {
                uint32_t r0, r1, r2, r3;
                uint32_t o = (uint32_t)(wc * 64 + nj * 16 + (lane & 15)) * 128 + col;
                LDSM4(r0, r1, r2, r3, base + 16384 + swz128(o));
#pragma unroll
                for (int mi = 0; mi < 4; mi++) {
                    QMMA(acc[mi][2*nj],     a[mi], r0, r2);
                    QMMA(acc[mi][2*nj + 1], a[mi], r1, r3);
                }
            }
        }
        __syncthreads();
    }

    float sc = __ldg(sc_p);
    if (EPI == 1) {
#pragma unroll
        for (int mi = 0; mi < 4; mi++) {
            int r0 = bm + wr * 64 + mi * 16 + (lane >> 2);
            int r1 = r0 + 8;
            float s0 = 0.f, s1 = 0.f;
#pragma unroll
            for (int ni = 0; ni < 8; ni++) {
                int c = bn + wc * 64 + ni * 8 + (lane & 3) * 2;
                float g0 = gelu_exact(acc[mi][ni][0] * sc);
                float g1 = gelu_exact(acc[mi][ni][1] * sc);
                float g2 = gelu_exact(acc[mi][ni][2] * sc);
                float g3 = gelu_exact(acc[mi][ni][3] * sc);
                *(uint16_t*)(g_hidden + (size_t)r0 * HIDC + c) = f2e4m3x2(g0, g1);
                *(uint16_t*)(g_hidden + (size_t)r1 * HIDC + c) = f2e4m3x2(g2, g3);
                s0 += g0*g0 + g1*g1;
                s1 += g2*g2 + g3*g3;
            }
            s0 += __shfl_xor_sync(0xffffffffu, s0, 1);
            s0 += __shfl_xor_sync(0xffffffffu, s0, 2);
            s1 += __shfl_xor_sync(0xffffffffu, s1, 1);
            s1 += __shfl_xor_sync(0xffffffffu, s1, 2);
            if ((lane & 3) == 0) {
                atomicAdd(&g_rowsq[r0], s0);
                atomicAdd(&g_rowsq[r1], s1);
            }
        }
    } else {
#pragma unroll
        for (int mi = 0; mi < 4; mi++) {
            int r0 = bm + wr * 64 + mi * 16 + (lane >> 2);
            int r1 = r0 + 8;
            float inv0 = sc / fmaxf(sqrtf(g_rowsq[r0]), 1e-12f);
            float inv1 = sc / fmaxf(sqrtf(g_rowsq[r1]), 1e-12f);
#pragma unroll
            for (int ni = 0; ni < 8; ni++) {
                int cl = wc * 64 + ni * 8 + (lane & 3) * 2;
                int c = bn + cl;
                float ga0 = s_gam[cl], ga1 = s_gam[cl + 1];
                size_t i00 = (size_t)r0 * DIMC + c;
                size_t i10 = (size_t)r1 * DIMC + c;
                outp[i00]     += ga0 * acc[mi][ni][0] * inv0;
                outp[i00 + 1] += ga1 * acc[mi][ni][1] * inv0;
                outp[i10]     += ga0 * acc[mi][ni][2] * inv1;
                outp[i10 + 1] += ga1 * acc[mi][ni][3] * inv1;
            }
        }
    }
}

// ---------------- launch ----------------
extern "C" void kernel_launch(void* const* d_in, const int* in_sizes, int n_in,
                              void* d_out, int out_size) {
    const float* x     = (const float*)d_in[0];
    const float* n1w   = (const float*)d_in[1];
    const float* n1b   = (const float*)d_in[2];
    const float* alpha = (const float*)d_in[3];
    const float* n2w   = (const float*)d_in[4];
    const float* n2b   = (const float*)d_in[5];
    const float* pin   = (const float*)d_in[6];
    const float* pout  = (const float*)d_in[7];
    const float* s_in  = (const float*)d_in[8];
    const float* s_out = (const float*)d_in[9];
    const float* gamma = (const float*)d_in[10];
    float* out = (float*)d_out;

    cudaFuncSetAttribute(k_gemm_fp8<512, 1>,  cudaFuncAttributeMaxDynamicSharedMemorySize, NSTAGE*STGB);
    cudaFuncSetAttribute(k_gemm_fp8<1024, 2>, cudaFuncAttributeMaxDynamicSharedMemorySize, NSTAGE*STGB);

    kz<<<1, 256>>>();
    k_colsq<<<96, 256>>>(pin, pout);
    k_wtrans<<<512, 256>>>(pin, pout);
    k_ln1<<<NBATCH * 64, 256>>>(x, n1w, n1b);
    k_spatial<<<NBATCH * 64, 256>>>(x, alpha, n2w, n2b, gamma, out);
    k_gemm_fp8<512, 1><<<dim3(HIDC / 256, NPIX / 128), 256, NSTAGE*STGB>>>(s_in, nullptr, nullptr);
    k_gemm_fp8<1024, 2><<<dim3(DIMC / 256, NPIX / 128), 256, NSTAGE*STGB>>>(s_out, gamma, out);
}